// round 8
// baseline (speedup 1.0000x reference)
#include <cuda_runtime.h>
#include <math.h>

#define D 64

constexpr int N_NODES    = 100000;
constexpr int N_EDGES    = 800000;
constexpr int R_MOL      = 8;
constexpr int N_MOL      = 5000;
constexpr int N_RXN_EDGES= 40000;
constexpr int R_RXN      = 4;
constexpr int N_RXN      = 1024;
constexpr int DIM_HIDDEN = 512;
constexpr int DIM_OUT    = 703;

// ----- device-global scratch (no allocations allowed) -----
__device__ float g_hW  [(size_t)R_MOL * N_NODES * D];   // 204.8 MB, reused by mol layer
__device__ float g_h1  [(size_t)N_NODES * D];
__device__ float g_h2  [(size_t)N_NODES * D];
__device__ float g_atts[(size_t)R_MOL * N_NODES];
__device__ float g_attd[(size_t)R_MOL * N_NODES];
__device__ float g_sc  [N_EDGES];
__device__ float g_maxv[N_NODES];
__device__ float g_sumv[N_NODES];
__device__ float g_us  [R_MOL * D];
__device__ float g_ud  [R_MOL * D];
__device__ float g_mol [N_MOL * D];
__device__ float g_molr[N_MOL * D];
__device__ float g_feat[N_RXN * 2 * D];
__device__ float g_hm  [N_RXN * DIM_HIDDEN];

// ----- packed fp32x2 helpers (Blackwell dual-rate fp32; PTX-only path) -----
__device__ __forceinline__ unsigned long long pack2(float x, float y) {
    unsigned long long r;
    asm("mov.b64 %0,{%1,%2};" : "=l"(r) : "f"(x), "f"(y));
    return r;
}
__device__ __forceinline__ void fma2(unsigned long long& d,
                                     unsigned long long a, unsigned long long b) {
    asm("fma.rn.f32x2 %0,%1,%2,%0;" : "+l"(d) : "l"(a), "l"(b));
}
__device__ __forceinline__ float2 unpack2(unsigned long long v) {
    float2 u;
    asm("mov.b64 {%0,%1},%2;" : "=f"(u.x), "=f"(u.y) : "l"(v));
    return u;
}

// ---------------------------------------------------------------------------
// u_src[r,d] = sum_e W[r,d,e]*a_src[r,e]   (folds attention vectors through W)
__global__ void k_u(const float* __restrict__ W, const float* __restrict__ as_,
                    const float* __restrict__ ad_, float* __restrict__ us,
                    float* __restrict__ ud, int R)
{
    int i = threadIdx.x;
    if (i >= R * D) return;
    int r = i >> 6;
    const float* Wrow = W + (size_t)i * D;
    const float* a1 = as_ + r * D;
    const float* a2 = ad_ + r * D;
    float s = 0.f, t = 0.f;
#pragma unroll
    for (int e = 0; e < D; e++) { float w = Wrow[e]; s += w * a1[e]; t += w * a2[e]; }
    us[i] = s; ud[i] = t;
}

// att_s[r,n] = h[n] . u_src[r]
__global__ void __launch_bounds__(256) k_att(const float* __restrict__ h,
        const float* __restrict__ usg, const float* __restrict__ udg,
        float* __restrict__ atts, float* __restrict__ attd, int N, int R)
{
    __shared__ float us[R_MOL * D], ud[R_MOL * D];
    for (int i = threadIdx.x; i < R * D; i += 256) { us[i] = usg[i]; ud[i] = udg[i]; }
    __syncthreads();
    int n = blockIdx.x * 256 + threadIdx.x;
    if (n >= N) return;
    float hv[D];
    const float4* hp = (const float4*)(h + (size_t)n * D);
#pragma unroll
    for (int q = 0; q < D / 4; q++) {
        float4 v = hp[q];
        hv[4*q] = v.x; hv[4*q+1] = v.y; hv[4*q+2] = v.z; hv[4*q+3] = v.w;
    }
    for (int r = 0; r < R; r++) {
        float s = 0.f, t = 0.f;
#pragma unroll
        for (int d2 = 0; d2 < D; d2++) { s += hv[d2] * us[r*D + d2]; t += hv[d2] * ud[r*D + d2]; }
        atts[(size_t)r * N + n] = s;
        attd[(size_t)r * N + n] = t;
    }
}

// init max=-inf, sum=0, agg=0
__global__ void k_init(float* __restrict__ maxv, float* __restrict__ sumv,
                       float* __restrict__ agg, int N)
{
    int i = blockIdx.x * blockDim.x + threadIdx.x;
    if (i < N) { maxv[i] = __int_as_float(0xff800000); sumv[i] = 0.f; }
    if (i < N * D) agg[i] = 0.f;
}

// scores[e] = leaky_relu(att_s[rel,src]+att_d[rel,dst]); segment max into maxv[dst]
__global__ void k_scores(const int* __restrict__ src, const int* __restrict__ dst,
        const int* __restrict__ rel, const float* __restrict__ atts,
        const float* __restrict__ attd, float* __restrict__ sc,
        float* __restrict__ maxv, int E, int N)
{
    int e = blockIdx.x * blockDim.x + threadIdx.x;
    if (e >= E) return;
    int s = src[e], t = dst[e], r = rel[e];
    float x = atts[(size_t)r * N + s] + attd[(size_t)r * N + t];
    x = (x >= 0.f) ? x : 0.2f * x;
    sc[e] = x;
    if (x >= 0.f) atomicMax((int*)(maxv + t), __float_as_int(x));
    else          atomicMin((unsigned int*)(maxv + t), __float_as_uint(x));
}

// ex[e] = exp(score - max[dst]); segment sum into sumv[dst]
__global__ void k_expsum(const int* __restrict__ dst, float* __restrict__ sc,
        const float* __restrict__ maxv, float* __restrict__ sumv, int E)
{
    int e = blockIdx.x * blockDim.x + threadIdx.x;
    if (e >= E) return;
    int t = dst[e];
    float ex = __expf(sc[e] - maxv[t]);
    sc[e] = ex;
    atomicAdd(sumv + t, ex);
}

// sumv[i] = 1/(sumv[i]+1e-9)  (one reciprocal per node, not per edge/element)
__global__ void k_rcp(float* __restrict__ sumv, int N)
{
    int i = blockIdx.x * blockDim.x + threadIdx.x;
    if (i < N) sumv[i] = 1.f / (sumv[i] + 1e-9f);
}

// hW[r,n,:] = h[n,:] @ W[r]  — 128x64 tile, 128 thr, 8x8 f32x2 register tile
__global__ void __launch_bounds__(128) k_hw(const float* __restrict__ h,
        const float* __restrict__ W, float* __restrict__ hW, int N)
{
    __shared__ __align__(16) float Ws[64 * 64];    // 16 KB
    __shared__ __align__(16) float hT[64 * 128];   // 32 KB, [k][node]
    int r   = blockIdx.y;
    int n0  = blockIdx.x * 128;
    int tid = threadIdx.x;
    const float* Wr = W + (size_t)r * 4096;
#pragma unroll
    for (int i = 0; i < 32; i++) Ws[tid + i * 128] = Wr[tid + i * 128];
    // transpose-load h tile: thread tid owns node n0+tid (conflict-free STS)
    {
        int n = n0 + tid;
        if (n < N) {
            const float4* hp = (const float4*)(h + (size_t)n * 64);
#pragma unroll
            for (int j = 0; j < 16; j++) {
                float4 v = hp[j];
                hT[(4*j+0)*128 + tid] = v.x;
                hT[(4*j+1)*128 + tid] = v.y;
                hT[(4*j+2)*128 + tid] = v.z;
                hT[(4*j+3)*128 + tid] = v.w;
            }
        } else {
#pragma unroll
            for (int j = 0; j < 64; j++) hT[j * 128 + tid] = 0.f;
        }
    }
    __syncthreads();

    int i0 = (tid >> 3) * 8;   // node base (16 groups of 8 nodes)
    int e0 = (tid & 7) * 8;    // output base (8 groups of 8 outs)
    unsigned long long acc[4][8];   // [node-pair][out], f32x2 over node pair
#pragma unroll
    for (int i = 0; i < 4; i++)
#pragma unroll
        for (int j = 0; j < 8; j++) acc[i][j] = 0ull;

#pragma unroll 4
    for (int k = 0; k < 64; k++) {
        ulonglong2 ha = *(const ulonglong2*)&hT[k * 128 + i0];      // nodes i0..i0+3
        ulonglong2 hb = *(const ulonglong2*)&hT[k * 128 + i0 + 4];  // nodes i0+4..i0+7
        unsigned long long hp2[4] = { ha.x, ha.y, hb.x, hb.y };
        float4 w0 = *(const float4*)&Ws[k * 64 + e0];
        float4 w1 = *(const float4*)&Ws[k * 64 + e0 + 4];
        unsigned long long wb[8];
        wb[0] = pack2(w0.x, w0.x); wb[1] = pack2(w0.y, w0.y);
        wb[2] = pack2(w0.z, w0.z); wb[3] = pack2(w0.w, w0.w);
        wb[4] = pack2(w1.x, w1.x); wb[5] = pack2(w1.y, w1.y);
        wb[6] = pack2(w1.z, w1.z); wb[7] = pack2(w1.w, w1.w);
#pragma unroll
        for (int i = 0; i < 4; i++)
#pragma unroll
            for (int j = 0; j < 8; j++) fma2(acc[i][j], hp2[i], wb[j]);
    }

#pragma unroll
    for (int ip = 0; ip < 4; ip++) {
        float lo[8], hi[8];
#pragma unroll
        for (int j = 0; j < 8; j++) { float2 u = unpack2(acc[ip][j]); lo[j] = u.x; hi[j] = u.y; }
        int na = n0 + i0 + 2 * ip;
        if (na < N) {
            float4* o = (float4*)&hW[((size_t)r * N + (size_t)na) * 64 + e0];
            o[0] = make_float4(lo[0], lo[1], lo[2], lo[3]);
            o[1] = make_float4(lo[4], lo[5], lo[6], lo[7]);
        }
        int nb = na + 1;
        if (nb < N) {
            float4* o = (float4*)&hW[((size_t)r * N + (size_t)nb) * 64 + e0];
            o[0] = make_float4(hi[0], hi[1], hi[2], hi[3]);
            o[1] = make_float4(hi[4], hi[5], hi[6], hi[7]);
        }
    }
}

// agg[dst] += ex[e] * hW[rel,src]  (unnormalized; normalize per-node later)
__global__ void k_msg(const int* __restrict__ src, const int* __restrict__ dst,
        const int* __restrict__ rel, const float* __restrict__ sc,
        const float* __restrict__ hW, float* __restrict__ agg, int E, int N)
{
    long long idx = (long long)blockIdx.x * blockDim.x + threadIdx.x;
    int e = (int)(idx >> 4);
    if (e >= E) return;
    int c = ((int)idx & 15) << 2;
    int t = dst[e];
    float alpha = sc[e];
    const float4 v = *(const float4*)(hW + ((size_t)rel[e] * N + src[e]) * D + c);
    float4 m; m.x = alpha * v.x; m.y = alpha * v.y; m.z = alpha * v.z; m.w = alpha * v.w;
    float* o = agg + (size_t)t * D + c;
    asm volatile("red.global.add.v4.f32 [%0], {%1,%2,%3,%4};"
                 :: "l"(o), "f"(m.x), "f"(m.y), "f"(m.z), "f"(m.w) : "memory");
}

// h_out[i] = elu(agg[i] * rcp_sum[i>>6])
__global__ void k_norm_elu(float* __restrict__ a, const float* __restrict__ rsum, int n)
{
    int i = blockIdx.x * blockDim.x + threadIdx.x;
    if (i >= n) return;
    float x = a[i] * rsum[i >> 6];
    a[i] = (x > 0.f) ? x : (__expf(x) - 1.f);
}

__global__ void k_zero(float* __restrict__ a, int n)
{
    int i = blockIdx.x * blockDim.x + threadIdx.x;
    if (i < n) a[i] = 0.f;
}

// out[seg[n]*ostride + ooff + :] += x[n,:]
__global__ void k_seg4(const float* __restrict__ x, const int* __restrict__ seg,
        float* __restrict__ out, int N, int ostride, int ooff)
{
    long long idx = (long long)blockIdx.x * blockDim.x + threadIdx.x;
    int n = (int)(idx >> 4);
    if (n >= N) return;
    int c = ((int)idx & 15) << 2;
    const float4 v = *(const float4*)(x + (size_t)n * D + c);
    float* o = out + (size_t)seg[n] * ostride + ooff + c;
    asm volatile("red.global.add.v4.f32 [%0], {%1,%2,%3,%4};"
                 :: "l"(o), "f"(v.x), "f"(v.y), "f"(v.z), "f"(v.w) : "memory");
}

// C[M,Nn] = act(A[M,K] @ B[K,Nn] + bias); 64x64 tile, 256 thr, 4x4 f32x2 tile
__global__ void __launch_bounds__(256) k_gemm(const float* __restrict__ A,
        const float* __restrict__ B, const float* __restrict__ bias,
        float* __restrict__ C, int M, int Nn, int K, const float* __restrict__ prelu)
{
    __shared__ __align__(16) float As[16 * 68];
    __shared__ __align__(16) float Bs[16 * 64];
    int m0 = blockIdx.y * 64;
    int n0 = blockIdx.x * 64;
    int tid = threadIdx.x;
    int tx = tid & 15, ty = tid >> 4;
    unsigned long long acc[2][4];   // [m-pair][n], f32x2 over m pair
#pragma unroll
    for (int i = 0; i < 2; i++)
#pragma unroll
        for (int j = 0; j < 4; j++) acc[i][j] = 0ull;
    for (int k0 = 0; k0 < K; k0 += 16) {
        for (int i = tid; i < 1024; i += 256) {
            int ml = i >> 4, kk = i & 15;
            As[kk * 68 + ml] = A[(size_t)(m0 + ml) * K + (k0 + kk)];
        }
        for (int i = tid; i < 1024; i += 256) {
            int kk = i >> 6, nl = i & 63;
            int n = n0 + nl;
            Bs[kk * 64 + nl] = (n < Nn) ? B[(size_t)(k0 + kk) * Nn + n] : 0.f;
        }
        __syncthreads();
#pragma unroll
        for (int kk = 0; kk < 16; kk++) {
            ulonglong2 a2 = *(const ulonglong2*)&As[kk * 68 + ty * 4];
            unsigned long long am[2] = { a2.x, a2.y };
            float4 b = *(const float4*)&Bs[kk * 64 + tx * 4];
            unsigned long long wb[4];
            wb[0] = pack2(b.x, b.x); wb[1] = pack2(b.y, b.y);
            wb[2] = pack2(b.z, b.z); wb[3] = pack2(b.w, b.w);
#pragma unroll
            for (int i = 0; i < 2; i++)
#pragma unroll
                for (int j = 0; j < 4; j++) fma2(acc[i][j], am[i], wb[j]);
        }
        __syncthreads();
    }
    float p = prelu ? *prelu : 0.f;
    bool act = (prelu != nullptr);
#pragma unroll
    for (int i = 0; i < 2; i++) {
        int ma = m0 + ty * 4 + 2 * i;
#pragma unroll
        for (int j = 0; j < 4; j++) {
            int n = n0 + tx * 4 + j;
            if (n < Nn) {
                float2 u = unpack2(acc[i][j]);
                float va = u.x + bias[n];
                float vb = u.y + bias[n];
                if (act) { if (va < 0.f) va *= p; if (vb < 0.f) vb *= p; }
                C[(size_t)ma * Nn + n]       = va;
                C[(size_t)(ma + 1) * Nn + n] = vb;
            }
        }
    }
}

// ---------------------------------------------------------------------------
static void rgat(const float* h_in, float* h_out,
                 const int* src, const int* dst, const int* rel,
                 const float* W, const float* asrc, const float* adst,
                 int N, int E, int R,
                 float* hW, float* atts, float* attd, float* sc,
                 float* maxv, float* sumv, float* us, float* ud)
{
    k_u<<<1, R * D>>>(W, asrc, adst, us, ud, R);
    k_att<<<(N + 255) / 256, 256>>>(h_in, us, ud, atts, attd, N, R);
    k_init<<<(N * D + 255) / 256, 256>>>(maxv, sumv, h_out, N);
    k_scores<<<(E + 255) / 256, 256>>>(src, dst, rel, atts, attd, sc, maxv, E, N);
    k_expsum<<<(E + 255) / 256, 256>>>(dst, sc, maxv, sumv, E);
    k_rcp<<<(N + 255) / 256, 256>>>(sumv, N);
    dim3 g((N + 127) / 128, R);
    k_hw<<<g, 128>>>(h_in, W, hW, N);
    long long mt = (long long)E * 16;
    k_msg<<<(unsigned)((mt + 255) / 256), 256>>>(src, dst, rel, sc, hW, h_out, E, N);
    k_norm_elu<<<(N * D + 255) / 256, 256>>>(h_out, sumv, N * D);
}

template <typename T>
static float* sym(const T& s) { void* p = nullptr; cudaGetSymbolAddress(&p, s); return (float*)p; }

extern "C" void kernel_launch(void* const* d_in, const int* in_sizes, int n_in,
                              void* d_out, int out_size)
{
    const float* node_feats = (const float*)d_in[0];
    const int*   edge_src   = (const int*)d_in[1];
    const int*   edge_dst   = (const int*)d_in[2];
    const int*   edge_rel   = (const int*)d_in[3];
    const int*   node2mol   = (const int*)d_in[4];
    const int*   rxn_src    = (const int*)d_in[5];
    const int*   rxn_dst    = (const int*)d_in[6];
    const int*   rxn_rel    = (const int*)d_in[7];
    const int*   mol2rxn    = (const int*)d_in[8];
    const float* W1     = (const float*)d_in[9];
    const float* a_src1 = (const float*)d_in[10];
    const float* a_dst1 = (const float*)d_in[11];
    const float* W2     = (const float*)d_in[12];
    const float* a_src2 = (const float*)d_in[13];
    const float* a_dst2 = (const float*)d_in[14];
    const float* Wr     = (const float*)d_in[15];
    const float* a_srcr = (const float*)d_in[16];
    const float* a_dstr = (const float*)d_in[17];
    const float* w_fc1  = (const float*)d_in[18];
    const float* b_fc1  = (const float*)d_in[19];
    const float* prelu1 = (const float*)d_in[20];
    const float* w_fc2  = (const float*)d_in[21];
    const float* b_fc2  = (const float*)d_in[22];
    float* out = (float*)d_out;

    float* hW   = sym(g_hW);
    float* h1   = sym(g_h1);
    float* h2   = sym(g_h2);
    float* atts = sym(g_atts);
    float* attd = sym(g_attd);
    float* sc   = sym(g_sc);
    float* maxv = sym(g_maxv);
    float* sumv = sym(g_sumv);
    float* us   = sym(g_us);
    float* ud   = sym(g_ud);
    float* mol  = sym(g_mol);
    float* molr = sym(g_molr);
    float* feat = sym(g_feat);
    float* hm   = sym(g_hm);

    // atom-level RGAT layer 1 & 2
    rgat(node_feats, h1, edge_src, edge_dst, edge_rel, W1, a_src1, a_dst1,
         N_NODES, N_EDGES, R_MOL, hW, atts, attd, sc, maxv, sumv, us, ud);
    rgat(h1, h2, edge_src, edge_dst, edge_rel, W2, a_src2, a_dst2,
         N_NODES, N_EDGES, R_MOL, hW, atts, attd, sc, maxv, sumv, us, ud);

    // molecule readout: mol = segment_sum(h2, node2mol)
    k_zero<<<(N_MOL * D + 255) / 256, 256>>>(mol, N_MOL * D);
    k_seg4<<<(N_NODES * 16 + 255) / 256, 256>>>(h2, node2mol, mol, N_NODES, D, 0);

    // reaction-graph RGAT over molecules
    rgat(mol, molr, rxn_src, rxn_dst, rxn_rel, Wr, a_srcr, a_dstr,
         N_MOL, N_RXN_EDGES, R_RXN, hW, atts, attd, sc, maxv, sumv, us, ud);

    // reaction readout: feat = [segsum(molr), segsum(mol)]
    k_zero<<<(N_RXN * 2 * D + 255) / 256, 256>>>(feat, N_RXN * 2 * D);
    k_seg4<<<(N_MOL * 16 + 255) / 256, 256>>>(molr, mol2rxn, feat, N_MOL, 2 * D, 0);
    k_seg4<<<(N_MOL * 16 + 255) / 256, 256>>>(mol,  mol2rxn, feat, N_MOL, 2 * D, D);

    // MLP head
    k_gemm<<<dim3(DIM_HIDDEN / 64, N_RXN / 64), 256>>>(feat, w_fc1, b_fc1, hm,
                                                       N_RXN, DIM_HIDDEN, 2 * D, prelu1);
    k_gemm<<<dim3((DIM_OUT + 63) / 64, N_RXN / 64), 256>>>(hm, w_fc2, b_fc2, out,
                                                           N_RXN, DIM_OUT, DIM_HIDDEN, nullptr);
}

// round 12
// speedup vs baseline: 1.0073x; 1.0073x over previous
#include <cuda_runtime.h>
#include <math.h>

#define D 64

constexpr int N_NODES    = 100000;
constexpr int N_EDGES    = 800000;
constexpr int R_MOL      = 8;
constexpr int N_MOL      = 5000;
constexpr int N_RXN_EDGES= 40000;
constexpr int R_RXN      = 4;
constexpr int N_RXN      = 1024;
constexpr int DIM_HIDDEN = 512;
constexpr int DIM_OUT    = 703;

// ----- device-global scratch (no allocations allowed) -----
__device__ float g_hW  [(size_t)R_MOL * N_NODES * D];   // 204.8 MB, reused by mol layer
__device__ float g_h1  [(size_t)N_NODES * D];
__device__ float g_h2  [(size_t)N_NODES * D];
__device__ float g_atts[(size_t)R_MOL * N_NODES];
__device__ float g_attd[(size_t)R_MOL * N_NODES];
__device__ float g_sc  [N_EDGES];
__device__ float g_maxv[N_NODES];
__device__ float g_sumv[N_NODES];
__device__ float g_us  [R_MOL * D];
__device__ float g_ud  [R_MOL * D];
__device__ float g_mol [N_MOL * D];
__device__ float g_molr[N_MOL * D];
__device__ float g_feat[N_RXN * 2 * D];
__device__ float g_hm  [N_RXN * DIM_HIDDEN];

// ----- packed fp32x2 helpers (Blackwell dual-rate fp32; PTX-only path) -----
__device__ __forceinline__ unsigned long long pack2(float x, float y) {
    unsigned long long r;
    asm("mov.b64 %0,{%1,%2};" : "=l"(r) : "f"(x), "f"(y));
    return r;
}
__device__ __forceinline__ void fma2(unsigned long long& d,
                                     unsigned long long a, unsigned long long b) {
    asm("fma.rn.f32x2 %0,%1,%2,%0;" : "+l"(d) : "l"(a), "l"(b));
}
__device__ __forceinline__ float2 unpack2(unsigned long long v) {
    float2 u;
    asm("mov.b64 {%0,%1},%2;" : "=f"(u.x), "=f"(u.y) : "l"(v));
    return u;
}

// ---------------------------------------------------------------------------
// u_src[r,d] = sum_e W[r,d,e]*a_src[r,e]   (folds attention vectors through W)
__global__ void k_u(const float* __restrict__ W, const float* __restrict__ as_,
                    const float* __restrict__ ad_, float* __restrict__ us,
                    float* __restrict__ ud, int R)
{
    int i = threadIdx.x;
    if (i >= R * D) return;
    int r = i >> 6;
    const float* Wrow = W + (size_t)i * D;
    const float* a1 = as_ + r * D;
    const float* a2 = ad_ + r * D;
    float s = 0.f, t = 0.f;
#pragma unroll
    for (int e = 0; e < D; e++) { float w = Wrow[e]; s += w * a1[e]; t += w * a2[e]; }
    us[i] = s; ud[i] = t;
}

// att_s[r,n] = h[n] . u_src[r]
__global__ void __launch_bounds__(256) k_att(const float* __restrict__ h,
        const float* __restrict__ usg, const float* __restrict__ udg,
        float* __restrict__ atts, float* __restrict__ attd, int N, int R)
{
    __shared__ float us[R_MOL * D], ud[R_MOL * D];
    for (int i = threadIdx.x; i < R * D; i += 256) { us[i] = usg[i]; ud[i] = udg[i]; }
    __syncthreads();
    int n = blockIdx.x * 256 + threadIdx.x;
    if (n >= N) return;
    float hv[D];
    const float4* hp = (const float4*)(h + (size_t)n * D);
#pragma unroll
    for (int q = 0; q < D / 4; q++) {
        float4 v = hp[q];
        hv[4*q] = v.x; hv[4*q+1] = v.y; hv[4*q+2] = v.z; hv[4*q+3] = v.w;
    }
    for (int r = 0; r < R; r++) {
        float s = 0.f, t = 0.f;
#pragma unroll
        for (int d2 = 0; d2 < D; d2++) { s += hv[d2] * us[r*D + d2]; t += hv[d2] * ud[r*D + d2]; }
        atts[(size_t)r * N + n] = s;
        attd[(size_t)r * N + n] = t;
    }
}

// init max=-inf, sum=0, agg=0
__global__ void k_init(float* __restrict__ maxv, float* __restrict__ sumv,
                       float* __restrict__ agg, int N)
{
    int i = blockIdx.x * blockDim.x + threadIdx.x;
    if (i < N) { maxv[i] = __int_as_float(0xff800000); sumv[i] = 0.f; }
    if (i < N * D) agg[i] = 0.f;
}

// scores[e] = leaky_relu(att_s[rel,src]+att_d[rel,dst]); segment max into maxv[dst]
__global__ void k_scores(const int* __restrict__ src, const int* __restrict__ dst,
        const int* __restrict__ rel, const float* __restrict__ atts,
        const float* __restrict__ attd, float* __restrict__ sc,
        float* __restrict__ maxv, int E, int N)
{
    int e = blockIdx.x * blockDim.x + threadIdx.x;
    if (e >= E) return;
    int s = src[e], t = dst[e], r = rel[e];
    float x = atts[(size_t)r * N + s] + attd[(size_t)r * N + t];
    x = (x >= 0.f) ? x : 0.2f * x;
    sc[e] = x;
    if (x >= 0.f) atomicMax((int*)(maxv + t), __float_as_int(x));
    else          atomicMin((unsigned int*)(maxv + t), __float_as_uint(x));
}

// ex[e] = exp(score - max[dst]); segment sum into sumv[dst]
__global__ void k_expsum(const int* __restrict__ dst, float* __restrict__ sc,
        const float* __restrict__ maxv, float* __restrict__ sumv, int E)
{
    int e = blockIdx.x * blockDim.x + threadIdx.x;
    if (e >= E) return;
    int t = dst[e];
    float ex = __expf(sc[e] - maxv[t]);
    sc[e] = ex;
    atomicAdd(sumv + t, ex);
}

// sumv[i] = 1/(sumv[i]+1e-9)  (one reciprocal per node, not per edge/element)
__global__ void k_rcp(float* __restrict__ sumv, int N)
{
    int i = blockIdx.x * blockDim.x + threadIdx.x;
    if (i < N) sumv[i] = 1.f / (sumv[i] + 1e-9f);
}

// hW[r,n,:] = h[n,:] @ W[r]  — 128x64 tile, 128 thr, 8x8 f32x2 register tile
__global__ void __launch_bounds__(128) k_hw(const float* __restrict__ h,
        const float* __restrict__ W, float* __restrict__ hW, int N)
{
    __shared__ __align__(16) float Ws[64 * 64];    // 16 KB
    __shared__ __align__(16) float hT[64 * 128];   // 32 KB, [k][node]
    int r   = blockIdx.y;
    int n0  = blockIdx.x * 128;
    int tid = threadIdx.x;
    const float* Wr = W + (size_t)r * 4096;
#pragma unroll
    for (int i = 0; i < 32; i++) Ws[tid + i * 128] = Wr[tid + i * 128];
    // transpose-load h tile: thread tid owns node n0+tid (conflict-free STS)
    {
        int n = n0 + tid;
        if (n < N) {
            const float4* hp = (const float4*)(h + (size_t)n * 64);
#pragma unroll
            for (int j = 0; j < 16; j++) {
                float4 v = hp[j];
                hT[(4*j+0)*128 + tid] = v.x;
                hT[(4*j+1)*128 + tid] = v.y;
                hT[(4*j+2)*128 + tid] = v.z;
                hT[(4*j+3)*128 + tid] = v.w;
            }
        } else {
#pragma unroll
            for (int j = 0; j < 64; j++) hT[j * 128 + tid] = 0.f;
        }
    }
    __syncthreads();

    int i0 = (tid >> 3) * 8;   // node base (16 groups of 8 nodes)
    int e0 = (tid & 7) * 8;    // output base (8 groups of 8 outs)
    unsigned long long acc[4][8];   // [node-pair][out], f32x2 over node pair
#pragma unroll
    for (int i = 0; i < 4; i++)
#pragma unroll
        for (int j = 0; j < 8; j++) acc[i][j] = 0ull;

#pragma unroll 4
    for (int k = 0; k < 64; k++) {
        ulonglong2 ha = *(const ulonglong2*)&hT[k * 128 + i0];      // nodes i0..i0+3
        ulonglong2 hb = *(const ulonglong2*)&hT[k * 128 + i0 + 4];  // nodes i0+4..i0+7
        unsigned long long hp2[4] = { ha.x, ha.y, hb.x, hb.y };
        float4 w0 = *(const float4*)&Ws[k * 64 + e0];
        float4 w1 = *(const float4*)&Ws[k * 64 + e0 + 4];
        unsigned long long wb[8];
        wb[0] = pack2(w0.x, w0.x); wb[1] = pack2(w0.y, w0.y);
        wb[2] = pack2(w0.z, w0.z); wb[3] = pack2(w0.w, w0.w);
        wb[4] = pack2(w1.x, w1.x); wb[5] = pack2(w1.y, w1.y);
        wb[6] = pack2(w1.z, w1.z); wb[7] = pack2(w1.w, w1.w);
#pragma unroll
        for (int i = 0; i < 4; i++)
#pragma unroll
            for (int j = 0; j < 8; j++) fma2(acc[i][j], hp2[i], wb[j]);
    }

#pragma unroll
    for (int ip = 0; ip < 4; ip++) {
        float lo[8], hi[8];
#pragma unroll
        for (int j = 0; j < 8; j++) { float2 u = unpack2(acc[ip][j]); lo[j] = u.x; hi[j] = u.y; }
        int na = n0 + i0 + 2 * ip;
        if (na < N) {
            float4* o = (float4*)&hW[((size_t)r * N + (size_t)na) * 64 + e0];
            o[0] = make_float4(lo[0], lo[1], lo[2], lo[3]);
            o[1] = make_float4(lo[4], lo[5], lo[6], lo[7]);
        }
        int nb = na + 1;
        if (nb < N) {
            float4* o = (float4*)&hW[((size_t)r * N + (size_t)nb) * 64 + e0];
            o[0] = make_float4(hi[0], hi[1], hi[2], hi[3]);
            o[1] = make_float4(hi[4], hi[5], hi[6], hi[7]);
        }
    }
}

// agg[dst] += ex[e] * hW[rel,src]  (unnormalized; normalize per-node later)
__global__ void k_msg(const int* __restrict__ src, const int* __restrict__ dst,
        const int* __restrict__ rel, const float* __restrict__ sc,
        const float* __restrict__ hW, float* __restrict__ agg, int E, int N)
{
    long long idx = (long long)blockIdx.x * blockDim.x + threadIdx.x;
    int e = (int)(idx >> 4);
    if (e >= E) return;
    int c = ((int)idx & 15) << 2;
    int t = dst[e];
    float alpha = sc[e];
    const float4 v = *(const float4*)(hW + ((size_t)rel[e] * N + src[e]) * D + c);
    float4 m; m.x = alpha * v.x; m.y = alpha * v.y; m.z = alpha * v.z; m.w = alpha * v.w;
    float* o = agg + (size_t)t * D + c;
    asm volatile("red.global.add.v4.f32 [%0], {%1,%2,%3,%4};"
                 :: "l"(o), "f"(m.x), "f"(m.y), "f"(m.z), "f"(m.w) : "memory");
}

// h_out[i] = elu(agg[i] * rcp_sum[i>>6])
__global__ void k_norm_elu(float* __restrict__ a, const float* __restrict__ rsum, int n)
{
    int i = blockIdx.x * blockDim.x + threadIdx.x;
    if (i >= n) return;
    float x = a[i] * rsum[i >> 6];
    a[i] = (x > 0.f) ? x : (__expf(x) - 1.f);
}

__global__ void k_zero(float* __restrict__ a, int n)
{
    int i = blockIdx.x * blockDim.x + threadIdx.x;
    if (i < n) a[i] = 0.f;
}

// out[seg[n]*ostride + ooff + :] += x[n,:]
__global__ void k_seg4(const float* __restrict__ x, const int* __restrict__ seg,
        float* __restrict__ out, int N, int ostride, int ooff)
{
    long long idx = (long long)blockIdx.x * blockDim.x + threadIdx.x;
    int n = (int)(idx >> 4);
    if (n >= N) return;
    int c = ((int)idx & 15) << 2;
    const float4 v = *(const float4*)(x + (size_t)n * D + c);
    float* o = out + (size_t)seg[n] * ostride + ooff + c;
    asm volatile("red.global.add.v4.f32 [%0], {%1,%2,%3,%4};"
                 :: "l"(o), "f"(v.x), "f"(v.y), "f"(v.z), "f"(v.w) : "memory");
}

// C[M,Nn] = act(A[M,K] @ B[K,Nn] + bias); 64x64 tile, 256 thr, 4x4 f32x2 tile
__global__ void __launch_bounds__(256) k_gemm(const float* __restrict__ A,
        const float* __restrict__ B, const float* __restrict__ bias,
        float* __restrict__ C, int M, int Nn, int K, const float* __restrict__ prelu)
{
    __shared__ __align__(16) float As[16 * 68];
    __shared__ __align__(16) float Bs[16 * 64];
    int m0 = blockIdx.y * 64;
    int n0 = blockIdx.x * 64;
    int tid = threadIdx.x;
    int tx = tid & 15, ty = tid >> 4;
    unsigned long long acc[2][4];   // [m-pair][n], f32x2 over m pair
#pragma unroll
    for (int i = 0; i < 2; i++)
#pragma unroll
        for (int j = 0; j < 4; j++) acc[i][j] = 0ull;
    for (int k0 = 0; k0 < K; k0 += 16) {
        for (int i = tid; i < 1024; i += 256) {
            int ml = i >> 4, kk = i & 15;
            As[kk * 68 + ml] = A[(size_t)(m0 + ml) * K + (k0 + kk)];
        }
        for (int i = tid; i < 1024; i += 256) {
            int kk = i >> 6, nl = i & 63;
            int n = n0 + nl;
            Bs[kk * 64 + nl] = (n < Nn) ? B[(size_t)(k0 + kk) * Nn + n] : 0.f;
        }
        __syncthreads();
#pragma unroll
        for (int kk = 0; kk < 16; kk++) {
            ulonglong2 a2 = *(const ulonglong2*)&As[kk * 68 + ty * 4];
            unsigned long long am[2] = { a2.x, a2.y };
            float4 b = *(const float4*)&Bs[kk * 64 + tx * 4];
            unsigned long long wb[4];
            wb[0] = pack2(b.x, b.x); wb[1] = pack2(b.y, b.y);
            wb[2] = pack2(b.z, b.z); wb[3] = pack2(b.w, b.w);
#pragma unroll
            for (int i = 0; i < 2; i++)
#pragma unroll
                for (int j = 0; j < 4; j++) fma2(acc[i][j], am[i], wb[j]);
        }
        __syncthreads();
    }
    float p = prelu ? *prelu : 0.f;
    bool act = (prelu != nullptr);
#pragma unroll
    for (int i = 0; i < 2; i++) {
        int ma = m0 + ty * 4 + 2 * i;
#pragma unroll
        for (int j = 0; j < 4; j++) {
            int n = n0 + tx * 4 + j;
            if (n < Nn) {
                float2 u = unpack2(acc[i][j]);
                float va = u.x + bias[n];
                float vb = u.y + bias[n];
                if (act) { if (va < 0.f) va *= p; if (vb < 0.f) vb *= p; }
                C[(size_t)ma * Nn + n]       = va;
                C[(size_t)(ma + 1) * Nn + n] = vb;
            }
        }
    }
}

// ---------------------------------------------------------------------------
static void rgat(const float* h_in, float* h_out,
                 const int* src, const int* dst, const int* rel,
                 const float* W, const float* asrc, const float* adst,
                 int N, int E, int R,
                 float* hW, float* atts, float* attd, float* sc,
                 float* maxv, float* sumv, float* us, float* ud)
{
    k_u<<<1, R * D>>>(W, asrc, adst, us, ud, R);
    k_att<<<(N + 255) / 256, 256>>>(h_in, us, ud, atts, attd, N, R);
    k_init<<<(N * D + 255) / 256, 256>>>(maxv, sumv, h_out, N);
    k_scores<<<(E + 255) / 256, 256>>>(src, dst, rel, atts, attd, sc, maxv, E, N);
    k_expsum<<<(E + 255) / 256, 256>>>(dst, sc, maxv, sumv, E);
    k_rcp<<<(N + 255) / 256, 256>>>(sumv, N);
    dim3 g((N + 127) / 128, R);
    k_hw<<<g, 128>>>(h_in, W, hW, N);
    long long mt = (long long)E * 16;
    k_msg<<<(unsigned)((mt + 255) / 256), 256>>>(src, dst, rel, sc, hW, h_out, E, N);
    k_norm_elu<<<(N * D + 255) / 256, 256>>>(h_out, sumv, N * D);
}

template <typename T>
static float* sym(const T& s) { void* p = nullptr; cudaGetSymbolAddress(&p, s); return (float*)p; }

extern "C" void kernel_launch(void* const* d_in, const int* in_sizes, int n_in,
                              void* d_out, int out_size)
{
    const float* node_feats = (const float*)d_in[0];
    const int*   edge_src   = (const int*)d_in[1];
    const int*   edge_dst   = (const int*)d_in[2];
    const int*   edge_rel   = (const int*)d_in[3];
    const int*   node2mol   = (const int*)d_in[4];
    const int*   rxn_src    = (const int*)d_in[5];
    const int*   rxn_dst    = (const int*)d_in[6];
    const int*   rxn_rel    = (const int*)d_in[7];
    const int*   mol2rxn    = (const int*)d_in[8];
    const float* W1     = (const float*)d_in[9];
    const float* a_src1 = (const float*)d_in[10];
    const float* a_dst1 = (const float*)d_in[11];
    const float* W2     = (const float*)d_in[12];
    const float* a_src2 = (const float*)d_in[13];
    const float* a_dst2 = (const float*)d_in[14];
    const float* Wr     = (const float*)d_in[15];
    const float* a_srcr = (const float*)d_in[16];
    const float* a_dstr = (const float*)d_in[17];
    const float* w_fc1  = (const float*)d_in[18];
    const float* b_fc1  = (const float*)d_in[19];
    const float* prelu1 = (const float*)d_in[20];
    const float* w_fc2  = (const float*)d_in[21];
    const float* b_fc2  = (const float*)d_in[22];
    float* out = (float*)d_out;

    float* hW   = sym(g_hW);
    float* h1   = sym(g_h1);
    float* h2   = sym(g_h2);
    float* atts = sym(g_atts);
    float* attd = sym(g_attd);
    float* sc   = sym(g_sc);
    float* maxv = sym(g_maxv);
    float* sumv = sym(g_sumv);
    float* us   = sym(g_us);
    float* ud   = sym(g_ud);
    float* mol  = sym(g_mol);
    float* molr = sym(g_molr);
    float* feat = sym(g_feat);
    float* hm   = sym(g_hm);

    // atom-level RGAT layer 1 & 2
    rgat(node_feats, h1, edge_src, edge_dst, edge_rel, W1, a_src1, a_dst1,
         N_NODES, N_EDGES, R_MOL, hW, atts, attd, sc, maxv, sumv, us, ud);
    rgat(h1, h2, edge_src, edge_dst, edge_rel, W2, a_src2, a_dst2,
         N_NODES, N_EDGES, R_MOL, hW, atts, attd, sc, maxv, sumv, us, ud);

    // molecule readout: mol = segment_sum(h2, node2mol)
    k_zero<<<(N_MOL * D + 255) / 256, 256>>>(mol, N_MOL * D);
    k_seg4<<<(N_NODES * 16 + 255) / 256, 256>>>(h2, node2mol, mol, N_NODES, D, 0);

    // reaction-graph RGAT over molecules
    rgat(mol, molr, rxn_src, rxn_dst, rxn_rel, Wr, a_srcr, a_dstr,
         N_MOL, N_RXN_EDGES, R_RXN, hW, atts, attd, sc, maxv, sumv, us, ud);

    // reaction readout: feat = [segsum(molr), segsum(mol)]
    k_zero<<<(N_RXN * 2 * D + 255) / 256, 256>>>(feat, N_RXN * 2 * D);
    k_seg4<<<(N_MOL * 16 + 255) / 256, 256>>>(molr, mol2rxn, feat, N_MOL, 2 * D, 0);
    k_seg4<<<(N_MOL * 16 + 255) / 256, 256>>>(mol,  mol2rxn, feat, N_MOL, 2 * D, D);

    // MLP head
    k_gemm<<<dim3(DIM_HIDDEN / 64, N_RXN / 64), 256>>>(feat, w_fc1, b_fc1, hm,
                                                       N_RXN, DIM_HIDDEN, 2 * D, prelu1);
    k_gemm<<<dim3((DIM_OUT + 63) / 64, N_RXN / 64), 256>>>(hm, w_fc2, b_fc2, out,
                                                           N_RXN, DIM_OUT, DIM_HIDDEN, nullptr);
}

// round 16
// speedup vs baseline: 1.0075x; 1.0002x over previous
#include <cuda_runtime.h>
#include <math.h>

#define D 64

constexpr int N_NODES    = 100000;
constexpr int N_EDGES    = 800000;
constexpr int R_MOL      = 8;
constexpr int N_MOL      = 5000;
constexpr int N_RXN_EDGES= 40000;
constexpr int R_RXN      = 4;
constexpr int N_RXN      = 1024;
constexpr int DIM_HIDDEN = 512;
constexpr int DIM_OUT    = 703;

// ----- device-global scratch (no allocations allowed) -----
__device__ float g_hW  [(size_t)R_MOL * N_NODES * D];   // 204.8 MB, reused by mol layer
__device__ float g_h1  [(size_t)N_NODES * D];
__device__ float g_h2  [(size_t)N_NODES * D];
__device__ float g_atts[(size_t)R_MOL * N_NODES];
__device__ float g_attd[(size_t)R_MOL * N_NODES];
__device__ float g_sc  [N_EDGES];
__device__ float g_maxv[N_NODES];
__device__ float g_sumv[N_NODES];
__device__ float g_us  [R_MOL * D];
__device__ float g_ud  [R_MOL * D];
__device__ float g_mol [N_MOL * D];
__device__ float g_molr[N_MOL * D];
__device__ float g_feat[N_RXN * 2 * D];
__device__ float g_hm  [N_RXN * DIM_HIDDEN];

// ----- packed fp32x2 helpers (Blackwell dual-rate fp32; PTX-only path) -----
__device__ __forceinline__ unsigned long long pack2(float x, float y) {
    unsigned long long r;
    asm("mov.b64 %0,{%1,%2};" : "=l"(r) : "f"(x), "f"(y));
    return r;
}
__device__ __forceinline__ void fma2(unsigned long long& d,
                                     unsigned long long a, unsigned long long b) {
    asm("fma.rn.f32x2 %0,%1,%2,%0;" : "+l"(d) : "l"(a), "l"(b));
}
__device__ __forceinline__ float2 unpack2(unsigned long long v) {
    float2 u;
    asm("mov.b64 {%0,%1},%2;" : "=f"(u.x), "=f"(u.y) : "l"(v));
    return u;
}

// ---------------------------------------------------------------------------
// u_src[r,d] = sum_e W[r,d,e]*a_src[r,e]   (folds attention vectors through W)
__global__ void k_u(const float* __restrict__ W, const float* __restrict__ as_,
                    const float* __restrict__ ad_, float* __restrict__ us,
                    float* __restrict__ ud, int R)
{
    int i = threadIdx.x;
    if (i >= R * D) return;
    int r = i >> 6;
    const float* Wrow = W + (size_t)i * D;
    const float* a1 = as_ + r * D;
    const float* a2 = ad_ + r * D;
    float s = 0.f, t = 0.f;
#pragma unroll
    for (int e = 0; e < D; e++) { float w = Wrow[e]; s += w * a1[e]; t += w * a2[e]; }
    us[i] = s; ud[i] = t;
}

// att_s[r,n] = h[n] . u_src[r]
__global__ void __launch_bounds__(256) k_att(const float* __restrict__ h,
        const float* __restrict__ usg, const float* __restrict__ udg,
        float* __restrict__ atts, float* __restrict__ attd, int N, int R)
{
    __shared__ float us[R_MOL * D], ud[R_MOL * D];
    for (int i = threadIdx.x; i < R * D; i += 256) { us[i] = usg[i]; ud[i] = udg[i]; }
    __syncthreads();
    int n = blockIdx.x * 256 + threadIdx.x;
    if (n >= N) return;
    float hv[D];
    const float4* hp = (const float4*)(h + (size_t)n * D);
#pragma unroll
    for (int q = 0; q < D / 4; q++) {
        float4 v = hp[q];
        hv[4*q] = v.x; hv[4*q+1] = v.y; hv[4*q+2] = v.z; hv[4*q+3] = v.w;
    }
    for (int r = 0; r < R; r++) {
        float s = 0.f, t = 0.f;
#pragma unroll
        for (int d2 = 0; d2 < D; d2++) { s += hv[d2] * us[r*D + d2]; t += hv[d2] * ud[r*D + d2]; }
        atts[(size_t)r * N + n] = s;
        attd[(size_t)r * N + n] = t;
    }
}

// init max=-inf, sum=0, agg=0
__global__ void k_init(float* __restrict__ maxv, float* __restrict__ sumv,
                       float* __restrict__ agg, int N)
{
    int i = blockIdx.x * blockDim.x + threadIdx.x;
    if (i < N) { maxv[i] = __int_as_float(0xff800000); sumv[i] = 0.f; }
    if (i < N * D) agg[i] = 0.f;
}

// scores[e] = leaky_relu(att_s[rel,src]+att_d[rel,dst]); segment max into maxv[dst]
__global__ void k_scores(const int* __restrict__ src, const int* __restrict__ dst,
        const int* __restrict__ rel, const float* __restrict__ atts,
        const float* __restrict__ attd, float* __restrict__ sc,
        float* __restrict__ maxv, int E, int N)
{
    int e = blockIdx.x * blockDim.x + threadIdx.x;
    if (e >= E) return;
    int s = src[e], t = dst[e], r = rel[e];
    float x = atts[(size_t)r * N + s] + attd[(size_t)r * N + t];
    x = (x >= 0.f) ? x : 0.2f * x;
    sc[e] = x;
    if (x >= 0.f) atomicMax((int*)(maxv + t), __float_as_int(x));
    else          atomicMin((unsigned int*)(maxv + t), __float_as_uint(x));
}

// ex[e] = exp(score - max[dst]); segment sum into sumv[dst]
__global__ void k_expsum(const int* __restrict__ dst, float* __restrict__ sc,
        const float* __restrict__ maxv, float* __restrict__ sumv, int E)
{
    int e = blockIdx.x * blockDim.x + threadIdx.x;
    if (e >= E) return;
    int t = dst[e];
    float ex = __expf(sc[e] - maxv[t]);
    sc[e] = ex;
    atomicAdd(sumv + t, ex);
}

// sumv[i] = 1/(sumv[i]+1e-9)  (one reciprocal per node, not per edge/element)
__global__ void k_rcp(float* __restrict__ sumv, int N)
{
    int i = blockIdx.x * blockDim.x + threadIdx.x;
    if (i < N) sumv[i] = 1.f / (sumv[i] + 1e-9f);
}

// hW[r,n,:] = h[n,:] @ W[r]  — 128x64 tile, 128 thr, 8x8 f32x2 register tile
__global__ void __launch_bounds__(128) k_hw(const float* __restrict__ h,
        const float* __restrict__ W, float* __restrict__ hW, int N)
{
    __shared__ __align__(16) float Ws[64 * 64];    // 16 KB
    __shared__ __align__(16) float hT[64 * 128];   // 32 KB, [k][node]
    int r   = blockIdx.y;
    int n0  = blockIdx.x * 128;
    int tid = threadIdx.x;
    const float* Wr = W + (size_t)r * 4096;
#pragma unroll
    for (int i = 0; i < 32; i++) Ws[tid + i * 128] = Wr[tid + i * 128];
    // transpose-load h tile: thread tid owns node n0+tid (conflict-free STS)
    {
        int n = n0 + tid;
        if (n < N) {
            const float4* hp = (const float4*)(h + (size_t)n * 64);
#pragma unroll
            for (int j = 0; j < 16; j++) {
                float4 v = hp[j];
                hT[(4*j+0)*128 + tid] = v.x;
                hT[(4*j+1)*128 + tid] = v.y;
                hT[(4*j+2)*128 + tid] = v.z;
                hT[(4*j+3)*128 + tid] = v.w;
            }
        } else {
#pragma unroll
            for (int j = 0; j < 64; j++) hT[j * 128 + tid] = 0.f;
        }
    }
    __syncthreads();

    int i0 = (tid >> 3) * 8;   // node base (16 groups of 8 nodes)
    int e0 = (tid & 7) * 8;    // output base (8 groups of 8 outs)
    unsigned long long acc[4][8];   // [node-pair][out], f32x2 over node pair
#pragma unroll
    for (int i = 0; i < 4; i++)
#pragma unroll
        for (int j = 0; j < 8; j++) acc[i][j] = 0ull;

#pragma unroll 4
    for (int k = 0; k < 64; k++) {
        ulonglong2 ha = *(const ulonglong2*)&hT[k * 128 + i0];      // nodes i0..i0+3
        ulonglong2 hb = *(const ulonglong2*)&hT[k * 128 + i0 + 4];  // nodes i0+4..i0+7
        unsigned long long hp2[4] = { ha.x, ha.y, hb.x, hb.y };
        float4 w0 = *(const float4*)&Ws[k * 64 + e0];
        float4 w1 = *(const float4*)&Ws[k * 64 + e0 + 4];
        unsigned long long wb[8];
        wb[0] = pack2(w0.x, w0.x); wb[1] = pack2(w0.y, w0.y);
        wb[2] = pack2(w0.z, w0.z); wb[3] = pack2(w0.w, w0.w);
        wb[4] = pack2(w1.x, w1.x); wb[5] = pack2(w1.y, w1.y);
        wb[6] = pack2(w1.z, w1.z); wb[7] = pack2(w1.w, w1.w);
#pragma unroll
        for (int i = 0; i < 4; i++)
#pragma unroll
            for (int j = 0; j < 8; j++) fma2(acc[i][j], hp2[i], wb[j]);
    }

#pragma unroll
    for (int ip = 0; ip < 4; ip++) {
        float lo[8], hi[8];
#pragma unroll
        for (int j = 0; j < 8; j++) { float2 u = unpack2(acc[ip][j]); lo[j] = u.x; hi[j] = u.y; }
        int na = n0 + i0 + 2 * ip;
        if (na < N) {
            float4* o = (float4*)&hW[((size_t)r * N + (size_t)na) * 64 + e0];
            o[0] = make_float4(lo[0], lo[1], lo[2], lo[3]);
            o[1] = make_float4(lo[4], lo[5], lo[6], lo[7]);
        }
        int nb = na + 1;
        if (nb < N) {
            float4* o = (float4*)&hW[((size_t)r * N + (size_t)nb) * 64 + e0];
            o[0] = make_float4(hi[0], hi[1], hi[2], hi[3]);
            o[1] = make_float4(hi[4], hi[5], hi[6], hi[7]);
        }
    }
}

// agg[dst] += ex[e] * hW[rel,src]  (unnormalized; normalize per-node later)
__global__ void k_msg(const int* __restrict__ src, const int* __restrict__ dst,
        const int* __restrict__ rel, const float* __restrict__ sc,
        const float* __restrict__ hW, float* __restrict__ agg, int E, int N)
{
    long long idx = (long long)blockIdx.x * blockDim.x + threadIdx.x;
    int e = (int)(idx >> 4);
    if (e >= E) return;
    int c = ((int)idx & 15) << 2;
    int t = dst[e];
    float alpha = sc[e];
    const float4 v = *(const float4*)(hW + ((size_t)rel[e] * N + src[e]) * D + c);
    float4 m; m.x = alpha * v.x; m.y = alpha * v.y; m.z = alpha * v.z; m.w = alpha * v.w;
    float* o = agg + (size_t)t * D + c;
    asm volatile("red.global.add.v4.f32 [%0], {%1,%2,%3,%4};"
                 :: "l"(o), "f"(m.x), "f"(m.y), "f"(m.z), "f"(m.w) : "memory");
}

// h_out[i] = elu(agg[i] * rcp_sum[i>>6])
__global__ void k_norm_elu(float* __restrict__ a, const float* __restrict__ rsum, int n)
{
    int i = blockIdx.x * blockDim.x + threadIdx.x;
    if (i >= n) return;
    float x = a[i] * rsum[i >> 6];
    a[i] = (x > 0.f) ? x : (__expf(x) - 1.f);
}

__global__ void k_zero(float* __restrict__ a, int n)
{
    int i = blockIdx.x * blockDim.x + threadIdx.x;
    if (i < n) a[i] = 0.f;
}

// out[seg[n]*ostride + ooff + :] += x[n,:]
__global__ void k_seg4(const float* __restrict__ x, const int* __restrict__ seg,
        float* __restrict__ out, int N, int ostride, int ooff)
{
    long long idx = (long long)blockIdx.x * blockDim.x + threadIdx.x;
    int n = (int)(idx >> 4);
    if (n >= N) return;
    int c = ((int)idx & 15) << 2;
    const float4 v = *(const float4*)(x + (size_t)n * D + c);
    float* o = out + (size_t)seg[n] * ostride + ooff + c;
    asm volatile("red.global.add.v4.f32 [%0], {%1,%2,%3,%4};"
                 :: "l"(o), "f"(v.x), "f"(v.y), "f"(v.z), "f"(v.w) : "memory");
}

// C[M,Nn] = act(A[M,K] @ B[K,Nn] + bias); 64x64 tile, 256 thr, 4x4 f32x2 tile
__global__ void __launch_bounds__(256) k_gemm(const float* __restrict__ A,
        const float* __restrict__ B, const float* __restrict__ bias,
        float* __restrict__ C, int M, int Nn, int K, const float* __restrict__ prelu)
{
    __shared__ __align__(16) float As[16 * 68];
    __shared__ __align__(16) float Bs[16 * 64];
    int m0 = blockIdx.y * 64;
    int n0 = blockIdx.x * 64;
    int tid = threadIdx.x;
    int tx = tid & 15, ty = tid >> 4;
    unsigned long long acc[2][4];   // [m-pair][n], f32x2 over m pair
#pragma unroll
    for (int i = 0; i < 2; i++)
#pragma unroll
        for (int j = 0; j < 4; j++) acc[i][j] = 0ull;
    for (int k0 = 0; k0 < K; k0 += 16) {
        for (int i = tid; i < 1024; i += 256) {
            int ml = i >> 4, kk = i & 15;
            As[kk * 68 + ml] = A[(size_t)(m0 + ml) * K + (k0 + kk)];
        }
        for (int i = tid; i < 1024; i += 256) {
            int kk = i >> 6, nl = i & 63;
            int n = n0 + nl;
            Bs[kk * 64 + nl] = (n < Nn) ? B[(size_t)(k0 + kk) * Nn + n] : 0.f;
        }
        __syncthreads();
#pragma unroll
        for (int kk = 0; kk < 16; kk++) {
            ulonglong2 a2 = *(const ulonglong2*)&As[kk * 68 + ty * 4];
            unsigned long long am[2] = { a2.x, a2.y };
            float4 b = *(const float4*)&Bs[kk * 64 + tx * 4];
            unsigned long long wb[4];
            wb[0] = pack2(b.x, b.x); wb[1] = pack2(b.y, b.y);
            wb[2] = pack2(b.z, b.z); wb[3] = pack2(b.w, b.w);
#pragma unroll
            for (int i = 0; i < 2; i++)
#pragma unroll
                for (int j = 0; j < 4; j++) fma2(acc[i][j], am[i], wb[j]);
        }
        __syncthreads();
    }
    float p = prelu ? *prelu : 0.f;
    bool act = (prelu != nullptr);
#pragma unroll
    for (int i = 0; i < 2; i++) {
        int ma = m0 + ty * 4 + 2 * i;
#pragma unroll
        for (int j = 0; j < 4; j++) {
            int n = n0 + tx * 4 + j;
            if (n < Nn) {
                float2 u = unpack2(acc[i][j]);
                float va = u.x + bias[n];
                float vb = u.y + bias[n];
                if (act) { if (va < 0.f) va *= p; if (vb < 0.f) vb *= p; }
                C[(size_t)ma * Nn + n]       = va;
                C[(size_t)(ma + 1) * Nn + n] = vb;
            }
        }
    }
}

// ---------------------------------------------------------------------------
static void rgat(const float* h_in, float* h_out,
                 const int* src, const int* dst, const int* rel,
                 const float* W, const float* asrc, const float* adst,
                 int N, int E, int R,
                 float* hW, float* atts, float* attd, float* sc,
                 float* maxv, float* sumv, float* us, float* ud)
{
    k_u<<<1, R * D>>>(W, asrc, adst, us, ud, R);
    k_att<<<(N + 255) / 256, 256>>>(h_in, us, ud, atts, attd, N, R);
    k_init<<<(N * D + 255) / 256, 256>>>(maxv, sumv, h_out, N);
    k_scores<<<(E + 255) / 256, 256>>>(src, dst, rel, atts, attd, sc, maxv, E, N);
    k_expsum<<<(E + 255) / 256, 256>>>(dst, sc, maxv, sumv, E);
    k_rcp<<<(N + 255) / 256, 256>>>(sumv, N);
    dim3 g((N + 127) / 128, R);
    k_hw<<<g, 128>>>(h_in, W, hW, N);
    long long mt = (long long)E * 16;
    k_msg<<<(unsigned)((mt + 255) / 256), 256>>>(src, dst, rel, sc, hW, h_out, E, N);
    k_norm_elu<<<(N * D + 255) / 256, 256>>>(h_out, sumv, N * D);
}

template <typename T>
static float* sym(const T& s) { void* p = nullptr; cudaGetSymbolAddress(&p, s); return (float*)p; }

extern "C" void kernel_launch(void* const* d_in, const int* in_sizes, int n_in,
                              void* d_out, int out_size)
{
    const float* node_feats = (const float*)d_in[0];
    const int*   edge_src   = (const int*)d_in[1];
    const int*   edge_dst   = (const int*)d_in[2];
    const int*   edge_rel   = (const int*)d_in[3];
    const int*   node2mol   = (const int*)d_in[4];
    const int*   rxn_src    = (const int*)d_in[5];
    const int*   rxn_dst    = (const int*)d_in[6];
    const int*   rxn_rel    = (const int*)d_in[7];
    const int*   mol2rxn    = (const int*)d_in[8];
    const float* W1     = (const float*)d_in[9];
    const float* a_src1 = (const float*)d_in[10];
    const float* a_dst1 = (const float*)d_in[11];
    const float* W2     = (const float*)d_in[12];
    const float* a_src2 = (const float*)d_in[13];
    const float* a_dst2 = (const float*)d_in[14];
    const float* Wr     = (const float*)d_in[15];
    const float* a_srcr = (const float*)d_in[16];
    const float* a_dstr = (const float*)d_in[17];
    const float* w_fc1  = (const float*)d_in[18];
    const float* b_fc1  = (const float*)d_in[19];
    const float* prelu1 = (const float*)d_in[20];
    const float* w_fc2  = (const float*)d_in[21];
    const float* b_fc2  = (const float*)d_in[22];
    float* out = (float*)d_out;

    float* hW   = sym(g_hW);
    float* h1   = sym(g_h1);
    float* h2   = sym(g_h2);
    float* atts = sym(g_atts);
    float* attd = sym(g_attd);
    float* sc   = sym(g_sc);
    float* maxv = sym(g_maxv);
    float* sumv = sym(g_sumv);
    float* us   = sym(g_us);
    float* ud   = sym(g_ud);
    float* mol  = sym(g_mol);
    float* molr = sym(g_molr);
    float* feat = sym(g_feat);
    float* hm   = sym(g_hm);

    // atom-level RGAT layer 1 & 2
    rgat(node_feats, h1, edge_src, edge_dst, edge_rel, W1, a_src1, a_dst1,
         N_NODES, N_EDGES, R_MOL, hW, atts, attd, sc, maxv, sumv, us, ud);
    rgat(h1, h2, edge_src, edge_dst, edge_rel, W2, a_src2, a_dst2,
         N_NODES, N_EDGES, R_MOL, hW, atts, attd, sc, maxv, sumv, us, ud);

    // molecule readout: mol = segment_sum(h2, node2mol)
    k_zero<<<(N_MOL * D + 255) / 256, 256>>>(mol, N_MOL * D);
    k_seg4<<<(N_NODES * 16 + 255) / 256, 256>>>(h2, node2mol, mol, N_NODES, D, 0);

    // reaction-graph RGAT over molecules
    rgat(mol, molr, rxn_src, rxn_dst, rxn_rel, Wr, a_srcr, a_dstr,
         N_MOL, N_RXN_EDGES, R_RXN, hW, atts, attd, sc, maxv, sumv, us, ud);

    // reaction readout: feat = [segsum(molr), segsum(mol)]
    k_zero<<<(N_RXN * 2 * D + 255) / 256, 256>>>(feat, N_RXN * 2 * D);
    k_seg4<<<(N_MOL * 16 + 255) / 256, 256>>>(molr, mol2rxn, feat, N_MOL, 2 * D, 0);
    k_seg4<<<(N_MOL * 16 + 255) / 256, 256>>>(mol,  mol2rxn, feat, N_MOL, 2 * D, D);

    // MLP head
    k_gemm<<<dim3(DIM_HIDDEN / 64, N_RXN / 64), 256>>>(feat, w_fc1, b_fc1, hm,
                                                       N_RXN, DIM_HIDDEN, 2 * D, prelu1);
    k_gemm<<<dim3((DIM_OUT + 63) / 64, N_RXN / 64), 256>>>(hm, w_fc2, b_fc2, out,
                                                           N_RXN, DIM_OUT, DIM_HIDDEN, nullptr);
}

// round 17
// speedup vs baseline: 1.0078x; 1.0003x over previous
#include <cuda_runtime.h>
#include <math.h>

#define D 64

constexpr int N_NODES    = 100000;
constexpr int N_EDGES    = 800000;
constexpr int R_MOL      = 8;
constexpr int N_MOL      = 5000;
constexpr int N_RXN_EDGES= 40000;
constexpr int R_RXN      = 4;
constexpr int N_RXN      = 1024;
constexpr int DIM_HIDDEN = 512;
constexpr int DIM_OUT    = 703;

// ----- device-global scratch (no allocations allowed) -----
__device__ float g_hW  [(size_t)R_MOL * N_NODES * D];   // 204.8 MB, reused by mol layer
__device__ float g_h1  [(size_t)N_NODES * D];
__device__ float g_h2  [(size_t)N_NODES * D];
__device__ float g_atts[(size_t)R_MOL * N_NODES];
__device__ float g_attd[(size_t)R_MOL * N_NODES];
__device__ float g_sc  [N_EDGES];
__device__ float g_maxv[N_NODES];
__device__ float g_sumv[N_NODES];
__device__ float g_us  [R_MOL * D];
__device__ float g_ud  [R_MOL * D];
__device__ float g_mol [N_MOL * D];
__device__ float g_molr[N_MOL * D];
__device__ float g_feat[N_RXN * 2 * D];
__device__ float g_hm  [N_RXN * DIM_HIDDEN];

// ----- packed fp32x2 helpers (Blackwell dual-rate fp32; PTX-only path) -----
__device__ __forceinline__ unsigned long long pack2(float x, float y) {
    unsigned long long r;
    asm("mov.b64 %0,{%1,%2};" : "=l"(r) : "f"(x), "f"(y));
    return r;
}
__device__ __forceinline__ void fma2(unsigned long long& d,
                                     unsigned long long a, unsigned long long b) {
    asm("fma.rn.f32x2 %0,%1,%2,%0;" : "+l"(d) : "l"(a), "l"(b));
}
__device__ __forceinline__ float2 unpack2(unsigned long long v) {
    float2 u;
    asm("mov.b64 {%0,%1},%2;" : "=f"(u.x), "=f"(u.y) : "l"(v));
    return u;
}

// ---------------------------------------------------------------------------
// u_src[r,d] = sum_e W[r,d,e]*a_src[r,e]   (folds attention vectors through W)
__global__ void k_u(const float* __restrict__ W, const float* __restrict__ as_,
                    const float* __restrict__ ad_, float* __restrict__ us,
                    float* __restrict__ ud, int R)
{
    int i = threadIdx.x;
    if (i >= R * D) return;
    int r = i >> 6;
    const float* Wrow = W + (size_t)i * D;
    const float* a1 = as_ + r * D;
    const float* a2 = ad_ + r * D;
    float s = 0.f, t = 0.f;
#pragma unroll
    for (int e = 0; e < D; e++) { float w = Wrow[e]; s += w * a1[e]; t += w * a2[e]; }
    us[i] = s; ud[i] = t;
}

// att_s[r,n] = h[n] . u_src[r]
__global__ void __launch_bounds__(256) k_att(const float* __restrict__ h,
        const float* __restrict__ usg, const float* __restrict__ udg,
        float* __restrict__ atts, float* __restrict__ attd, int N, int R)
{
    __shared__ float us[R_MOL * D], ud[R_MOL * D];
    for (int i = threadIdx.x; i < R * D; i += 256) { us[i] = usg[i]; ud[i] = udg[i]; }
    __syncthreads();
    int n = blockIdx.x * 256 + threadIdx.x;
    if (n >= N) return;
    float hv[D];
    const float4* hp = (const float4*)(h + (size_t)n * D);
#pragma unroll
    for (int q = 0; q < D / 4; q++) {
        float4 v = hp[q];
        hv[4*q] = v.x; hv[4*q+1] = v.y; hv[4*q+2] = v.z; hv[4*q+3] = v.w;
    }
    for (int r = 0; r < R; r++) {
        float s = 0.f, t = 0.f;
#pragma unroll
        for (int d2 = 0; d2 < D; d2++) { s += hv[d2] * us[r*D + d2]; t += hv[d2] * ud[r*D + d2]; }
        atts[(size_t)r * N + n] = s;
        attd[(size_t)r * N + n] = t;
    }
}

// init max=-inf, sum=0, agg=0
__global__ void k_init(float* __restrict__ maxv, float* __restrict__ sumv,
                       float* __restrict__ agg, int N)
{
    int i = blockIdx.x * blockDim.x + threadIdx.x;
    if (i < N) { maxv[i] = __int_as_float(0xff800000); sumv[i] = 0.f; }
    if (i < N * D) agg[i] = 0.f;
}

// scores[e] = leaky_relu(att_s[rel,src]+att_d[rel,dst]); segment max into maxv[dst]
__global__ void k_scores(const int* __restrict__ src, const int* __restrict__ dst,
        const int* __restrict__ rel, const float* __restrict__ atts,
        const float* __restrict__ attd, float* __restrict__ sc,
        float* __restrict__ maxv, int E, int N)
{
    int e = blockIdx.x * blockDim.x + threadIdx.x;
    if (e >= E) return;
    int s = src[e], t = dst[e], r = rel[e];
    float x = atts[(size_t)r * N + s] + attd[(size_t)r * N + t];
    x = (x >= 0.f) ? x : 0.2f * x;
    sc[e] = x;
    if (x >= 0.f) atomicMax((int*)(maxv + t), __float_as_int(x));
    else          atomicMin((unsigned int*)(maxv + t), __float_as_uint(x));
}

// ex[e] = exp(score - max[dst]); segment sum into sumv[dst]
__global__ void k_expsum(const int* __restrict__ dst, float* __restrict__ sc,
        const float* __restrict__ maxv, float* __restrict__ sumv, int E)
{
    int e = blockIdx.x * blockDim.x + threadIdx.x;
    if (e >= E) return;
    int t = dst[e];
    float ex = __expf(sc[e] - maxv[t]);
    sc[e] = ex;
    atomicAdd(sumv + t, ex);
}

// sumv[i] = 1/(sumv[i]+1e-9)  (one reciprocal per node, not per edge/element)
__global__ void k_rcp(float* __restrict__ sumv, int N)
{
    int i = blockIdx.x * blockDim.x + threadIdx.x;
    if (i < N) sumv[i] = 1.f / (sumv[i] + 1e-9f);
}

// hW[r,n,:] = h[n,:] @ W[r]  — 128x64 tile, 128 thr, 8x8 f32x2 register tile
__global__ void __launch_bounds__(128) k_hw(const float* __restrict__ h,
        const float* __restrict__ W, float* __restrict__ hW, int N)
{
    __shared__ __align__(16) float Ws[64 * 64];    // 16 KB
    __shared__ __align__(16) float hT[64 * 128];   // 32 KB, [k][node]
    int r   = blockIdx.y;
    int n0  = blockIdx.x * 128;
    int tid = threadIdx.x;
    const float* Wr = W + (size_t)r * 4096;
#pragma unroll
    for (int i = 0; i < 32; i++) Ws[tid + i * 128] = Wr[tid + i * 128];
    // transpose-load h tile: thread tid owns node n0+tid (conflict-free STS)
    {
        int n = n0 + tid;
        if (n < N) {
            const float4* hp = (const float4*)(h + (size_t)n * 64);
#pragma unroll
            for (int j = 0; j < 16; j++) {
                float4 v = hp[j];
                hT[(4*j+0)*128 + tid] = v.x;
                hT[(4*j+1)*128 + tid] = v.y;
                hT[(4*j+2)*128 + tid] = v.z;
                hT[(4*j+3)*128 + tid] = v.w;
            }
        } else {
#pragma unroll
            for (int j = 0; j < 64; j++) hT[j * 128 + tid] = 0.f;
        }
    }
    __syncthreads();

    int i0 = (tid >> 3) * 8;   // node base (16 groups of 8 nodes)
    int e0 = (tid & 7) * 8;    // output base (8 groups of 8 outs)
    unsigned long long acc[4][8];   // [node-pair][out], f32x2 over node pair
#pragma unroll
    for (int i = 0; i < 4; i++)
#pragma unroll
        for (int j = 0; j < 8; j++) acc[i][j] = 0ull;

#pragma unroll 4
    for (int k = 0; k < 64; k++) {
        ulonglong2 ha = *(const ulonglong2*)&hT[k * 128 + i0];      // nodes i0..i0+3
        ulonglong2 hb = *(const ulonglong2*)&hT[k * 128 + i0 + 4];  // nodes i0+4..i0+7
        unsigned long long hp2[4] = { ha.x, ha.y, hb.x, hb.y };
        float4 w0 = *(const float4*)&Ws[k * 64 + e0];
        float4 w1 = *(const float4*)&Ws[k * 64 + e0 + 4];
        unsigned long long wb[8];
        wb[0] = pack2(w0.x, w0.x); wb[1] = pack2(w0.y, w0.y);
        wb[2] = pack2(w0.z, w0.z); wb[3] = pack2(w0.w, w0.w);
        wb[4] = pack2(w1.x, w1.x); wb[5] = pack2(w1.y, w1.y);
        wb[6] = pack2(w1.z, w1.z); wb[7] = pack2(w1.w, w1.w);
#pragma unroll
        for (int i = 0; i < 4; i++)
#pragma unroll
            for (int j = 0; j < 8; j++) fma2(acc[i][j], hp2[i], wb[j]);
    }

#pragma unroll
    for (int ip = 0; ip < 4; ip++) {
        float lo[8], hi[8];
#pragma unroll
        for (int j = 0; j < 8; j++) { float2 u = unpack2(acc[ip][j]); lo[j] = u.x; hi[j] = u.y; }
        int na = n0 + i0 + 2 * ip;
        if (na < N) {
            float4* o = (float4*)&hW[((size_t)r * N + (size_t)na) * 64 + e0];
            o[0] = make_float4(lo[0], lo[1], lo[2], lo[3]);
            o[1] = make_float4(lo[4], lo[5], lo[6], lo[7]);
        }
        int nb = na + 1;
        if (nb < N) {
            float4* o = (float4*)&hW[((size_t)r * N + (size_t)nb) * 64 + e0];
            o[0] = make_float4(hi[0], hi[1], hi[2], hi[3]);
            o[1] = make_float4(hi[4], hi[5], hi[6], hi[7]);
        }
    }
}

// agg[dst] += ex[e] * hW[rel,src]  (unnormalized; normalize per-node later)
__global__ void k_msg(const int* __restrict__ src, const int* __restrict__ dst,
        const int* __restrict__ rel, const float* __restrict__ sc,
        const float* __restrict__ hW, float* __restrict__ agg, int E, int N)
{
    long long idx = (long long)blockIdx.x * blockDim.x + threadIdx.x;
    int e = (int)(idx >> 4);
    if (e >= E) return;
    int c = ((int)idx & 15) << 2;
    int t = dst[e];
    float alpha = sc[e];
    const float4 v = *(const float4*)(hW + ((size_t)rel[e] * N + src[e]) * D + c);
    float4 m; m.x = alpha * v.x; m.y = alpha * v.y; m.z = alpha * v.z; m.w = alpha * v.w;
    float* o = agg + (size_t)t * D + c;
    asm volatile("red.global.add.v4.f32 [%0], {%1,%2,%3,%4};"
                 :: "l"(o), "f"(m.x), "f"(m.y), "f"(m.z), "f"(m.w) : "memory");
}

// h_out[i] = elu(agg[i] * rcp_sum[i>>6])
__global__ void k_norm_elu(float* __restrict__ a, const float* __restrict__ rsum, int n)
{
    int i = blockIdx.x * blockDim.x + threadIdx.x;
    if (i >= n) return;
    float x = a[i] * rsum[i >> 6];
    a[i] = (x > 0.f) ? x : (__expf(x) - 1.f);
}

__global__ void k_zero(float* __restrict__ a, int n)
{
    int i = blockIdx.x * blockDim.x + threadIdx.x;
    if (i < n) a[i] = 0.f;
}

// out[seg[n]*ostride + ooff + :] += x[n,:]
__global__ void k_seg4(const float* __restrict__ x, const int* __restrict__ seg,
        float* __restrict__ out, int N, int ostride, int ooff)
{
    long long idx = (long long)blockIdx.x * blockDim.x + threadIdx.x;
    int n = (int)(idx >> 4);
    if (n >= N) return;
    int c = ((int)idx & 15) << 2;
    const float4 v = *(const float4*)(x + (size_t)n * D + c);
    float* o = out + (size_t)seg[n] * ostride + ooff + c;
    asm volatile("red.global.add.v4.f32 [%0], {%1,%2,%3,%4};"
                 :: "l"(o), "f"(v.x), "f"(v.y), "f"(v.z), "f"(v.w) : "memory");
}

// C[M,Nn] = act(A[M,K] @ B[K,Nn] + bias); 64x64 tile, 256 thr, 4x4 f32x2 tile
__global__ void __launch_bounds__(256) k_gemm(const float* __restrict__ A,
        const float* __restrict__ B, const float* __restrict__ bias,
        float* __restrict__ C, int M, int Nn, int K, const float* __restrict__ prelu)
{
    __shared__ __align__(16) float As[16 * 68];
    __shared__ __align__(16) float Bs[16 * 64];
    int m0 = blockIdx.y * 64;
    int n0 = blockIdx.x * 64;
    int tid = threadIdx.x;
    int tx = tid & 15, ty = tid >> 4;
    unsigned long long acc[2][4];   // [m-pair][n], f32x2 over m pair
#pragma unroll
    for (int i = 0; i < 2; i++)
#pragma unroll
        for (int j = 0; j < 4; j++) acc[i][j] = 0ull;
    for (int k0 = 0; k0 < K; k0 += 16) {
        for (int i = tid; i < 1024; i += 256) {
            int ml = i >> 4, kk = i & 15;
            As[kk * 68 + ml] = A[(size_t)(m0 + ml) * K + (k0 + kk)];
        }
        for (int i = tid; i < 1024; i += 256) {
            int kk = i >> 6, nl = i & 63;
            int n = n0 + nl;
            Bs[kk * 64 + nl] = (n < Nn) ? B[(size_t)(k0 + kk) * Nn + n] : 0.f;
        }
        __syncthreads();
#pragma unroll
        for (int kk = 0; kk < 16; kk++) {
            ulonglong2 a2 = *(const ulonglong2*)&As[kk * 68 + ty * 4];
            unsigned long long am[2] = { a2.x, a2.y };
            float4 b = *(const float4*)&Bs[kk * 64 + tx * 4];
            unsigned long long wb[4];
            wb[0] = pack2(b.x, b.x); wb[1] = pack2(b.y, b.y);
            wb[2] = pack2(b.z, b.z); wb[3] = pack2(b.w, b.w);
#pragma unroll
            for (int i = 0; i < 2; i++)
#pragma unroll
                for (int j = 0; j < 4; j++) fma2(acc[i][j], am[i], wb[j]);
        }
        __syncthreads();
    }
    float p = prelu ? *prelu : 0.f;
    bool act = (prelu != nullptr);
#pragma unroll
    for (int i = 0; i < 2; i++) {
        int ma = m0 + ty * 4 + 2 * i;
#pragma unroll
        for (int j = 0; j < 4; j++) {
            int n = n0 + tx * 4 + j;
            if (n < Nn) {
                float2 u = unpack2(acc[i][j]);
                float va = u.x + bias[n];
                float vb = u.y + bias[n];
                if (act) { if (va < 0.f) va *= p; if (vb < 0.f) vb *= p; }
                C[(size_t)ma * Nn + n]       = va;
                C[(size_t)(ma + 1) * Nn + n] = vb;
            }
        }
    }
}

// ---------------------------------------------------------------------------
static void rgat(const float* h_in, float* h_out,
                 const int* src, const int* dst, const int* rel,
                 const float* W, const float* asrc, const float* adst,
                 int N, int E, int R,
                 float* hW, float* atts, float* attd, float* sc,
                 float* maxv, float* sumv, float* us, float* ud)
{
    k_u<<<1, R * D>>>(W, asrc, adst, us, ud, R);
    k_att<<<(N + 255) / 256, 256>>>(h_in, us, ud, atts, attd, N, R);
    k_init<<<(N * D + 255) / 256, 256>>>(maxv, sumv, h_out, N);
    k_scores<<<(E + 255) / 256, 256>>>(src, dst, rel, atts, attd, sc, maxv, E, N);
    k_expsum<<<(E + 255) / 256, 256>>>(dst, sc, maxv, sumv, E);
    k_rcp<<<(N + 255) / 256, 256>>>(sumv, N);
    dim3 g((N + 127) / 128, R);
    k_hw<<<g, 128>>>(h_in, W, hW, N);
    long long mt = (long long)E * 16;
    k_msg<<<(unsigned)((mt + 255) / 256), 256>>>(src, dst, rel, sc, hW, h_out, E, N);
    k_norm_elu<<<(N * D + 255) / 256, 256>>>(h_out, sumv, N * D);
}

template <typename T>
static float* sym(const T& s) { void* p = nullptr; cudaGetSymbolAddress(&p, s); return (float*)p; }

extern "C" void kernel_launch(void* const* d_in, const int* in_sizes, int n_in,
                              void* d_out, int out_size)
{
    const float* node_feats = (const float*)d_in[0];
    const int*   edge_src   = (const int*)d_in[1];
    const int*   edge_dst   = (const int*)d_in[2];
    const int*   edge_rel   = (const int*)d_in[3];
    const int*   node2mol   = (const int*)d_in[4];
    const int*   rxn_src    = (const int*)d_in[5];
    const int*   rxn_dst    = (const int*)d_in[6];
    const int*   rxn_rel    = (const int*)d_in[7];
    const int*   mol2rxn    = (const int*)d_in[8];
    const float* W1     = (const float*)d_in[9];
    const float* a_src1 = (const float*)d_in[10];
    const float* a_dst1 = (const float*)d_in[11];
    const float* W2     = (const float*)d_in[12];
    const float* a_src2 = (const float*)d_in[13];
    const float* a_dst2 = (const float*)d_in[14];
    const float* Wr     = (const float*)d_in[15];
    const float* a_srcr = (const float*)d_in[16];
    const float* a_dstr = (const float*)d_in[17];
    const float* w_fc1  = (const float*)d_in[18];
    const float* b_fc1  = (const float*)d_in[19];
    const float* prelu1 = (const float*)d_in[20];
    const float* w_fc2  = (const float*)d_in[21];
    const float* b_fc2  = (const float*)d_in[22];
    float* out = (float*)d_out;

    float* hW   = sym(g_hW);
    float* h1   = sym(g_h1);
    float* h2   = sym(g_h2);
    float* atts = sym(g_atts);
    float* attd = sym(g_attd);
    float* sc   = sym(g_sc);
    float* maxv = sym(g_maxv);
    float* sumv = sym(g_sumv);
    float* us   = sym(g_us);
    float* ud   = sym(g_ud);
    float* mol  = sym(g_mol);
    float* molr = sym(g_molr);
    float* feat = sym(g_feat);
    float* hm   = sym(g_hm);

    // atom-level RGAT layer 1 & 2
    rgat(node_feats, h1, edge_src, edge_dst, edge_rel, W1, a_src1, a_dst1,
         N_NODES, N_EDGES, R_MOL, hW, atts, attd, sc, maxv, sumv, us, ud);
    rgat(h1, h2, edge_src, edge_dst, edge_rel, W2, a_src2, a_dst2,
         N_NODES, N_EDGES, R_MOL, hW, atts, attd, sc, maxv, sumv, us, ud);

    // molecule readout: mol = segment_sum(h2, node2mol)
    k_zero<<<(N_MOL * D + 255) / 256, 256>>>(mol, N_MOL * D);
    k_seg4<<<(N_NODES * 16 + 255) / 256, 256>>>(h2, node2mol, mol, N_NODES, D, 0);

    // reaction-graph RGAT over molecules
    rgat(mol, molr, rxn_src, rxn_dst, rxn_rel, Wr, a_srcr, a_dstr,
         N_MOL, N_RXN_EDGES, R_RXN, hW, atts, attd, sc, maxv, sumv, us, ud);

    // reaction readout: feat = [segsum(molr), segsum(mol)]
    k_zero<<<(N_RXN * 2 * D + 255) / 256, 256>>>(feat, N_RXN * 2 * D);
    k_seg4<<<(N_MOL * 16 + 255) / 256, 256>>>(molr, mol2rxn, feat, N_MOL, 2 * D, 0);
    k_seg4<<<(N_MOL * 16 + 255) / 256, 256>>>(mol,  mol2rxn, feat, N_MOL, 2 * D, D);

    // MLP head
    k_gemm<<<dim3(DIM_HIDDEN / 64, N_RXN / 64), 256>>>(feat, w_fc1, b_fc1, hm,
                                                       N_RXN, DIM_HIDDEN, 2 * D, prelu1);
    k_gemm<<<dim3((DIM_OUT + 63) / 64, N_RXN / 64), 256>>>(hm, w_fc2, b_fc2, out,
                                                           N_RXN, DIM_OUT, DIM_HIDDEN, nullptr);
}